// round 4
// baseline (speedup 1.0000x reference)
#include <cuda_runtime.h>
#include <cstdint>

#define NTILES 8192            // 524288 pixels / 64 per tile
#define EPSV   1e-6f

// smem in float4 units, 65-pitch padded rows (1040 B: rotates bank groups)
// sA: [64 pixels][65]  float4 = (act_k, act_k+4, g_k, g_k+4), col = k8*4+q
// sW: [128 o   ][65]  float4 = (wx_k, wx_k+4, wy_k, wy_k+4)
#define PITCH  65
#define OFF_W  (64 * PITCH)            // 4160 float4
#define SMEM_F4 (64 * PITCH + 128 * PITCH)   // 12480 f4 = 199680 B

__device__ __forceinline__ float tf32r(float f) {
    uint32_t u; asm("cvt.rna.tf32.f32 %0, %1;" : "=r"(u) : "f"(f));
    return __uint_as_float(u);
}

__device__ __forceinline__ void mma_tf32(float* c, float a0, float a1, float a2, float a3,
                                         float b0, float b1) {
    asm volatile(
        "mma.sync.aligned.m16n8k8.row.col.f32.tf32.tf32.f32 "
        "{%0,%1,%2,%3},{%4,%5,%6,%7},{%8,%9},{%0,%1,%2,%3};\n"
        : "+f"(c[0]), "+f"(c[1]), "+f"(c[2]), "+f"(c[3])
        : "r"(__float_as_uint(a0)), "r"(__float_as_uint(a1)),
          "r"(__float_as_uint(a2)), "r"(__float_as_uint(a3)),
          "r"(__float_as_uint(b0)), "r"(__float_as_uint(b1)));
}

__global__ __launch_bounds__(256, 1)
void avnn_p4(const float* __restrict__ x,
             const float* __restrict__ wx,
             const float* __restrict__ bx,
             const float* __restrict__ wy,
             const float* __restrict__ by,
             float2* __restrict__ out) {
    extern __shared__ float4 smem[];
    float4* sA = smem;
    float4* sW = smem + OFF_W;

    const int tid = threadIdx.x, wid = tid >> 5, lane = tid & 31;
    const int gid = lane >> 2, q = lane & 3;

    // ---- stage weights once (tf32, interleaved float4) ----
    #pragma unroll 4
    for (int idx = tid; idx < 128 * 128; idx += 256) {
        int o = idx >> 7, c = idx & 127;
        int k8 = c >> 3, r = c & 7;
        int qq = r & 3, half = r >> 2;
        float* dst = (float*)&sW[o * PITCH + k8 * 4 + qq];
        dst[half]     = tf32r(wx[idx]);
        dst[2 + half] = tf32r(wy[idx]);
    }

    // ---- per-thread constants ----
    const int mbase = (wid & 1) * 32;      // pixel base (2 M-warps)
    const int nbase = (wid >> 1) * 32;     // o base     (4 N-warps)

    float bxv[4][2], byv[4][2];
    #pragma unroll
    for (int nt = 0; nt < 4; nt++) {
        int o0 = nbase + nt * 8 + 2 * q;
        bxv[nt][0] = __ldg(bx + o0); bxv[nt][1] = __ldg(bx + o0 + 1);
        byv[nt][0] = __ldg(by + o0); byv[nt][1] = __ldg(by + o0 + 1);
    }

    // fragment base pointers
    const float4* pA = sA + (mbase + gid) * PITCH + q;
    const float4* pB = sW + (nbase + gid) * PITCH + q;

    const float2* xv = (const float2*)x;
    const int grid = gridDim.x;

    int t = blockIdx.x;
    float2 rx[2][16];

    // prefetch first tile: warp wid owns c in [wid*16, wid*16+16), lane = pixel
    {
        int b = t >> 10, pp = (t & 1023) << 6;
        const float2* xb = xv + (((size_t)(b * 128 + wid * 16)) << 16) + pp + lane;
        #pragma unroll
        for (int j = 0; j < 16; j++) {
            rx[0][j] = __ldg(xb + ((size_t)j << 16));
            rx[1][j] = __ldg(xb + ((size_t)j << 16) + 32);
        }
    }

    for (;;) {
        // ---- transform + store tile t into smem (16 STS.128/thread) ----
        #pragma unroll
        for (int h = 0; h < 2; h++) {
            const int p = lane + 32 * h;
            float4* pa = sA + p * PITCH;
            #pragma unroll
            for (int kg = 0; kg < 2; kg++) {
                const int col0 = (wid * 2 + kg) * 4;
                #pragma unroll
                for (int qq2 = 0; qq2 < 4; qq2++) {
                    float2 vlo = rx[h][kg * 8 + qq2];
                    float2 vhi = rx[h][kg * 8 + qq2 + 4];
                    float4 st;
                    st.x = tf32r(vlo.x);
                    st.y = tf32r(vhi.x);
                    st.z = tf32r(__fdividef(vlo.x * vlo.y, fabsf(vlo.x) + EPSV));
                    st.w = tf32r(__fdividef(vhi.x * vhi.y, fabsf(vhi.x) + EPSV));
                    pa[col0 + qq2] = st;
                }
            }
        }
        __syncthreads();

        // ---- prefetch tile t+grid (hides under MMA loop) ----
        const int tn = t + grid;
        if (tn < NTILES) {
            int b = tn >> 10, pp = (tn & 1023) << 6;
            const float2* xb = xv + (((size_t)(b * 128 + wid * 16)) << 16) + pp + lane;
            #pragma unroll
            for (int j = 0; j < 16; j++) {
                rx[0][j] = __ldg(xb + ((size_t)j << 16));
                rx[1][j] = __ldg(xb + ((size_t)j << 16) + 32);
            }
        }

        // ---- compute: warp tile 32 pix x 32 o, both gemms, K=128 ----
        float acc[2][2][4][4];
        #pragma unroll
        for (int g = 0; g < 2; g++)
            #pragma unroll
            for (int mt = 0; mt < 2; mt++)
                #pragma unroll
                for (int nt = 0; nt < 4; nt++)
                    #pragma unroll
                    for (int i = 0; i < 4; i++) acc[g][mt][nt][i] = 0.f;

        #pragma unroll
        for (int k8 = 0; k8 < 16; k8++) {
            const int c4 = k8 * 4;
            float4 A0 = pA[c4];
            float4 A1 = pA[8  * PITCH + c4];
            float4 A2 = pA[16 * PITCH + c4];
            float4 A3 = pA[24 * PITCH + c4];
            float4 B0 = pB[c4];
            float4 B1 = pB[8  * PITCH + c4];
            float4 B2 = pB[16 * PITCH + c4];
            float4 B3 = pB[24 * PITCH + c4];

            // act GEMM
            mma_tf32(acc[0][0][0], A0.x, A1.x, A0.y, A1.y, B0.x, B0.y);
            mma_tf32(acc[0][0][1], A0.x, A1.x, A0.y, A1.y, B1.x, B1.y);
            mma_tf32(acc[0][0][2], A0.x, A1.x, A0.y, A1.y, B2.x, B2.y);
            mma_tf32(acc[0][0][3], A0.x, A1.x, A0.y, A1.y, B3.x, B3.y);
            mma_tf32(acc[0][1][0], A2.x, A3.x, A2.y, A3.y, B0.x, B0.y);
            mma_tf32(acc[0][1][1], A2.x, A3.x, A2.y, A3.y, B1.x, B1.y);
            mma_tf32(acc[0][1][2], A2.x, A3.x, A2.y, A3.y, B2.x, B2.y);
            mma_tf32(acc[0][1][3], A2.x, A3.x, A2.y, A3.y, B3.x, B3.y);
            // carry GEMM
            mma_tf32(acc[1][0][0], A0.z, A1.z, A0.w, A1.w, B0.z, B0.w);
            mma_tf32(acc[1][0][1], A0.z, A1.z, A0.w, A1.w, B1.z, B1.w);
            mma_tf32(acc[1][0][2], A0.z, A1.z, A0.w, A1.w, B2.z, B2.w);
            mma_tf32(acc[1][0][3], A0.z, A1.z, A0.w, A1.w, B3.z, B3.w);
            mma_tf32(acc[1][1][0], A2.z, A3.z, A2.w, A3.w, B0.z, B0.w);
            mma_tf32(acc[1][1][1], A2.z, A3.z, A2.w, A3.w, B1.z, B1.w);
            mma_tf32(acc[1][1][2], A2.z, A3.z, A2.w, A3.w, B2.z, B2.w);
            mma_tf32(acc[1][1][3], A2.z, A3.z, A2.w, A3.w, B3.z, B3.w);
        }

        // ---- epilogue: bias + relu, float2{act, carry} stores ----
        {
            const int b = t >> 10, pp = (t & 1023) << 6;
            const size_t tb = ((size_t)b << 23) + (size_t)pp;
            #pragma unroll
            for (int nt = 0; nt < 4; nt++) {
                const int o0 = nbase + nt * 8 + 2 * q;
                #pragma unroll
                for (int io = 0; io < 2; io++) {
                    float2* rowp = out + tb + ((size_t)(o0 + io) << 16);
                    #pragma unroll
                    for (int mt = 0; mt < 2; mt++) {
                        #pragma unroll
                        for (int ih = 0; ih < 2; ih++) {
                            const int pix = mbase + mt * 16 + gid + ih * 8;
                            float a = acc[0][mt][nt][ih * 2 + io] + bxv[nt][io];
                            float g = acc[1][mt][nt][ih * 2 + io] + byv[nt][io];
                            rowp[pix] = make_float2(fmaxf(a, 0.f), g);
                        }
                    }
                }
            }
        }

        if (tn >= NTILES) break;
        t = tn;
        __syncthreads();   // protect smem before next tile's stores
    }
}

extern "C" void kernel_launch(void* const* d_in, const int* in_sizes, int n_in,
                              void* d_out, int out_size) {
    const float* x  = (const float*)d_in[0];
    const float* wx = (const float*)d_in[1];
    const float* bx = (const float*)d_in[2];
    const float* wy = (const float*)d_in[3];
    const float* by = (const float*)d_in[4];
    float2* out = (float2*)d_out;

    int nsm = 148;
    cudaDeviceGetAttribute(&nsm, cudaDevAttrMultiProcessorCount, 0);

    const size_t smem_bytes = SMEM_F4 * sizeof(float4);   // 199680
    cudaFuncSetAttribute(avnn_p4, cudaFuncAttributeMaxDynamicSharedMemorySize,
                         (int)smem_bytes);

    avnn_p4<<<nsm, 256, smem_bytes>>>(x, wx, bx, wy, by, out);
}

// round 5
// speedup vs baseline: 1.3228x; 1.3228x over previous
#include <cuda_runtime.h>
#include <cstdint>

#define NTILES 8192            // 524288 pixels / 64 per tile
#define EPSV   1e-6f
#define P2     68              // row pitch in float2 (544 B; 544 % 256 = 32 -> bank rotate)
#define SXBUF  (64 * P2)       // 4352 f2 per chunk buffer (64 channels x 64 px)
#define OFF_WX (2 * SXBUF)     // 8704 f2
#define OFF_WY (OFF_WX + 128 * P2)
#define SMEM_F2 (OFF_WY + 128 * P2)       // 26112 f2 = 208896 B
#define SXBUF_BYTES (SXBUF * 8)           // 34816

__device__ __forceinline__ float tf32f(float f) {
    uint32_t u; asm("cvt.rna.tf32.f32 %0, %1;" : "=r"(u) : "f"(f));
    return __uint_as_float(u);
}

__device__ __forceinline__ void mma_tf32(float* c, float a0, float a1, float a2, float a3,
                                         float b0, float b1) {
    asm volatile(
        "mma.sync.aligned.m16n8k8.row.col.f32.tf32.tf32.f32 "
        "{%0,%1,%2,%3},{%4,%5,%6,%7},{%8,%9},{%0,%1,%2,%3};\n"
        : "+f"(c[0]), "+f"(c[1]), "+f"(c[2]), "+f"(c[3])
        : "r"(__float_as_uint(a0)), "r"(__float_as_uint(a1)),
          "r"(__float_as_uint(a2)), "r"(__float_as_uint(a3)),
          "r"(__float_as_uint(b0)), "r"(__float_as_uint(b1)));
}

__device__ __forceinline__ void cpa16(uint32_t dst, const void* src) {
    asm volatile("cp.async.cg.shared.global [%0], [%1], 16;" :: "r"(dst), "l"(src));
}
#define CP_COMMIT() asm volatile("cp.async.commit_group;" ::: "memory")
#define CP_WAIT(N)  asm volatile("cp.async.wait_group %0;" :: "n"(N) : "memory")

__global__ __launch_bounds__(256, 1)
void avnn_p5(const float* __restrict__ x,
             const float* __restrict__ wx,
             const float* __restrict__ bx,
             const float* __restrict__ wy,
             const float* __restrict__ by,
             float2* __restrict__ out) {
    extern __shared__ float2 smem[];
    float2* sX0 = smem;
    float2* sX1 = smem + SXBUF;
    float2* sWx = smem + OFF_WX;
    float2* sWy = smem + OFF_WY;

    const int tid = threadIdx.x, wid = tid >> 5, lane = tid & 31;
    const int gid = lane >> 2, q = lane & 3;
    const int grid = gridDim.x;

    uint32_t sbase;
    asm("{ .reg .u64 t; cvta.to.shared.u64 t, %1; cvt.u32.u64 %0, t; }"
        : "=r"(sbase) : "l"((const void*)smem));

    // ---- stage weights once (tf32, float2 = (w[k], w[k+4])) ----
    #pragma unroll 4
    for (int idx = tid; idx < 128 * 128; idx += 256) {
        int o = idx >> 7, c = idx & 127;
        int k8 = c >> 3, r = c & 7, qq = r & 3, hi = r >> 2;
        ((float*)&sWx[o * P2 + k8 * 4 + qq])[hi] = tf32f(wx[idx]);
        ((float*)&sWy[o * P2 + k8 * 4 + qq])[hi] = tf32f(wy[idx]);
    }

    // ---- per-thread constants ----
    const int mbase = (wid & 1) * 32;      // pixel base (2 M-warps)
    const int nbase = (wid >> 1) * 32;     // o base     (4 N-warps)

    float bxv[4][2], byv[4][2];
    #pragma unroll
    for (int nt = 0; nt < 4; nt++) {
        int o0 = nbase + nt * 8 + 2 * q;
        bxv[nt][0] = __ldg(bx + o0); bxv[nt][1] = __ldg(bx + o0 + 1);
        byv[nt][0] = __ldg(by + o0); byv[nt][1] = __ldg(by + o0 + 1);
    }

    // fragment base pointers: A from c-major (a,g) tile, B from weights
    const float2* pA0 = sX0 + q * P2 + mbase + gid;
    const float2* pA1 = sX1 + q * P2 + mbase + gid;
    const float2* pBx = sWx + (nbase + gid) * P2 + q;
    const float2* pBy = sWy + (nbase + gid) * P2 + q;

    // in-place transform mapping: row = wid*8 + lane>>2, px = (lane&3) + 4j
    float2* tp0 = sX0 + (wid * 8 + (lane >> 2)) * P2 + (lane & 3);
    float2* tp1 = tp0 + SXBUF;

    // cp.async mapping: warp w, iter i -> row w + 8i, col16 = lane (full 512B row/warp)
    const uint32_t cprow = (uint32_t)wid;          // +8i
    const uint32_t cpcol = (uint32_t)lane * 16u;
    const char* xb = (const char*)x;

    int t = blockIdx.x;

    // issue chunk ch of tile tt into buffer buf
    #define ISSUE(buf, tt, ch) do { \
        int _b = (tt) >> 10, _p0 = ((tt) & 1023) << 6; \
        size_t _gb = (((size_t)(_b * 128 + (ch) * 64)) << 19) + ((size_t)_p0 << 3); \
        uint32_t _sb = sbase + (buf) * (uint32_t)SXBUF_BYTES + cpcol; \
        const char* _gp = xb + _gb + cpcol; \
        _Pragma("unroll") \
        for (int _i = 0; _i < 8; _i++) { \
            uint32_t _r = cprow + 8u * _i; \
            cpa16(_sb + _r * 544u, _gp + ((size_t)_r << 19)); \
        } \
        CP_COMMIT(); \
    } while (0)

    #define TRANSFORM(tp) do { \
        _Pragma("unroll") \
        for (int _j = 0; _j < 16; _j++) { \
            float2 _v = (tp)[4 * _j]; \
            float _g = __fdividef(_v.x * _v.y, fabsf(_v.x) + EPSV); \
            (tp)[4 * _j] = make_float2(tf32f(_v.x), tf32f(_g)); \
        } \
    } while (0)

    // one K-half (8 k8 steps) from buffer pA, weight cols starting at kbase
    #define MMA_HALF(pA, kbase) do { \
        _Pragma("unroll") \
        for (int k8l = 0; k8l < 8; k8l++) { \
            const float2* _a = (pA) + k8l * (8 * P2); \
            float2 A00 = _a[0];                    /* c, px      */ \
            float2 A01 = _a[8];                    /* c, px+8    */ \
            float2 A02 = _a[4 * P2];               /* c+4, px    */ \
            float2 A03 = _a[4 * P2 + 8];           /* c+4, px+8  */ \
            float2 A10 = _a[16];                   /* mt1 */ \
            float2 A11 = _a[24]; \
            float2 A12 = _a[4 * P2 + 16]; \
            float2 A13 = _a[4 * P2 + 24]; \
            const int _kc = ((kbase) + k8l) * 4; \
            float2 Bx0 = pBx[_kc], Bx1 = pBx[8 * P2 + _kc]; \
            float2 Bx2 = pBx[16 * P2 + _kc], Bx3 = pBx[24 * P2 + _kc]; \
            float2 By0 = pBy[_kc], By1 = pBy[8 * P2 + _kc]; \
            float2 By2 = pBy[16 * P2 + _kc], By3 = pBy[24 * P2 + _kc]; \
            mma_tf32(acc[0][0][0], A00.x, A01.x, A02.x, A03.x, Bx0.x, Bx0.y); \
            mma_tf32(acc[0][0][1], A00.x, A01.x, A02.x, A03.x, Bx1.x, Bx1.y); \
            mma_tf32(acc[0][0][2], A00.x, A01.x, A02.x, A03.x, Bx2.x, Bx2.y); \
            mma_tf32(acc[0][0][3], A00.x, A01.x, A02.x, A03.x, Bx3.x, Bx3.y); \
            mma_tf32(acc[0][1][0], A10.x, A11.x, A12.x, A13.x, Bx0.x, Bx0.y); \
            mma_tf32(acc[0][1][1], A10.x, A11.x, A12.x, A13.x, Bx1.x, Bx1.y); \
            mma_tf32(acc[0][1][2], A10.x, A11.x, A12.x, A13.x, Bx2.x, Bx2.y); \
            mma_tf32(acc[0][1][3], A10.x, A11.x, A12.x, A13.x, Bx3.x, Bx3.y); \
            mma_tf32(acc[1][0][0], A00.y, A01.y, A02.y, A03.y, By0.x, By0.y); \
            mma_tf32(acc[1][0][1], A00.y, A01.y, A02.y, A03.y, By1.x, By1.y); \
            mma_tf32(acc[1][0][2], A00.y, A01.y, A02.y, A03.y, By2.x, By2.y); \
            mma_tf32(acc[1][0][3], A00.y, A01.y, A02.y, A03.y, By3.x, By3.y); \
            mma_tf32(acc[1][1][0], A10.y, A11.y, A12.y, A13.y, By0.x, By0.y); \
            mma_tf32(acc[1][1][1], A10.y, A11.y, A12.y, A13.y, By1.x, By1.y); \
            mma_tf32(acc[1][1][2], A10.y, A11.y, A12.y, A13.y, By2.x, By2.y); \
            mma_tf32(acc[1][1][3], A10.y, A11.y, A12.y, A13.y, By3.x, By3.y); \
        } \
    } while (0)

    // ---- prologue: both chunks of first tile in flight ----
    ISSUE(0, t, 0);
    ISSUE(1, t, 1);

    for (;;) {
        CP_WAIT(1);                 // chunk0(t) arrived (chunk1 may be in flight)
        __syncthreads();
        TRANSFORM(tp0);
        __syncthreads();

        float acc[2][2][4][4];
        #pragma unroll
        for (int g = 0; g < 2; g++)
            #pragma unroll
            for (int mt = 0; mt < 2; mt++)
                #pragma unroll
                for (int nt = 0; nt < 4; nt++)
                    #pragma unroll
                    for (int i = 0; i < 4; i++) acc[g][mt][nt][i] = 0.f;

        MMA_HALF(pA0, 0);           // K 0..63

        CP_WAIT(0);                 // chunk1(t) arrived
        __syncthreads();            // + all warps done reading buf0
        const int tn = t + grid;
        if (tn < NTILES) ISSUE(0, tn, 0);   // refill buf0 for next tile

        TRANSFORM(tp1);
        __syncthreads();

        MMA_HALF(pA1, 8);           // K 64..127

        // ---- epilogue: bias + relu, float2{act, carry} stores ----
        {
            const int b = t >> 10, pp = (t & 1023) << 6;
            const size_t tb = ((size_t)b << 23) + (size_t)pp;
            #pragma unroll
            for (int nt = 0; nt < 4; nt++) {
                const int o0 = nbase + nt * 8 + 2 * q;
                #pragma unroll
                for (int io = 0; io < 2; io++) {
                    float2* rowp = out + tb + ((size_t)(o0 + io) << 16);
                    #pragma unroll
                    for (int mt = 0; mt < 2; mt++) {
                        #pragma unroll
                        for (int ih = 0; ih < 2; ih++) {
                            const int pix = mbase + mt * 16 + gid + ih * 8;
                            float a = acc[0][mt][nt][ih * 2 + io] + bxv[nt][io];
                            float g = acc[1][mt][nt][ih * 2 + io] + byv[nt][io];
                            rowp[pix] = make_float2(fmaxf(a, 0.f), g);
                        }
                    }
                }
            }
        }

        __syncthreads();            // all warps done reading buf1
        if (tn < NTILES) ISSUE(1, tn, 1);
        else break;
        t = tn;
    }
}

extern "C" void kernel_launch(void* const* d_in, const int* in_sizes, int n_in,
                              void* d_out, int out_size) {
    const float* x  = (const float*)d_in[0];
    const float* wx = (const float*)d_in[1];
    const float* bx = (const float*)d_in[2];
    const float* wy = (const float*)d_in[3];
    const float* by = (const float*)d_in[4];
    float2* out = (float2*)d_out;

    int nsm = 148;
    cudaDeviceGetAttribute(&nsm, cudaDevAttrMultiProcessorCount, 0);

    const size_t smem_bytes = SMEM_F2 * sizeof(float2);   // 208896
    cudaFuncSetAttribute(avnn_p5, cudaFuncAttributeMaxDynamicSharedMemorySize,
                         (int)smem_bytes);

    avnn_p5<<<nsm, 256, smem_bytes>>>(x, wx, bx, wy, by, out);
}

// round 6
// speedup vs baseline: 1.5820x; 1.1959x over previous
#include <cuda_runtime.h>
#include <cuda_fp16.h>
#include <cstdint>

#define NTILES 8192            // 524288 pixels / 64 per tile
#define EPSV   1e-6f

// smem byte offsets
#define RAWP_B   544           // raw chunk row pitch (68 float2)
#define S_RAW0   0
#define S_RAW1   34816
#define S_HALF0  69632         // 64 px rows x 256 B
#define S_HALF1  86016
#define S_W      102400        // 64 c-pair rows x 1056 B
#define WPITCH   1056
#define SMEM_TOTAL 169984

__device__ __forceinline__ void mma_f16(float* c, uint32_t a0, uint32_t a1,
                                        uint32_t a2, uint32_t a3,
                                        uint32_t b0, uint32_t b1) {
    asm volatile(
        "mma.sync.aligned.m16n8k16.row.col.f32.f16.f16.f32 "
        "{%0,%1,%2,%3},{%4,%5,%6,%7},{%8,%9},{%0,%1,%2,%3};\n"
        : "+f"(c[0]), "+f"(c[1]), "+f"(c[2]), "+f"(c[3])
        : "r"(a0), "r"(a1), "r"(a2), "r"(a3), "r"(b0), "r"(b1));
}

__device__ __forceinline__ void cpa16(uint32_t dst, const void* src) {
    asm volatile("cp.async.cg.shared.global [%0], [%1], 16;" :: "r"(dst), "l"(src));
}
#define CP_COMMIT() asm volatile("cp.async.commit_group;" ::: "memory")
#define CP_WAIT(N)  asm volatile("cp.async.wait_group %0;" :: "n"(N) : "memory")

__device__ __forceinline__ uint32_t h2u(__half2 h) {
    return *reinterpret_cast<uint32_t*>(&h);
}

__global__ __launch_bounds__(256, 1)
void avnn_h6(const float* __restrict__ x,
             const float* __restrict__ wx,
             const float* __restrict__ bx,
             const float* __restrict__ wy,
             const float* __restrict__ by,
             float2* __restrict__ out) {
    extern __shared__ char smem[];
    const float2* raw0 = (const float2*)(smem + S_RAW0);
    const float2* raw1 = (const float2*)(smem + S_RAW1);
    char* half0 = smem + S_HALF0;
    char* half1 = smem + S_HALF1;
    char* smW   = smem + S_W;

    const int tid = threadIdx.x, wid = tid >> 5, lane = tid & 31;
    const int gid = lane >> 2, q = lane & 3;
    const int grid = gridDim.x;

    uint32_t sbase;
    asm("{ .reg .u64 t; cvta.to.shared.u64 t, %1; cvt.u32.u64 %0, t; }"
        : "=r"(sbase) : "l"((const void*)smem));

    // ---- stage weights once: sW[cpair][o] = (wx_lo, wx_hi, wy_lo, wy_hi) halves ----
    #pragma unroll 4
    for (int idx = tid; idx < 128 * 128; idx += 256) {
        int o = idx >> 7, c = idx & 127;
        int cp = c >> 1, hi = c & 1;
        __half* w = (__half*)(smW + cp * WPITCH + o * 8);
        w[hi]     = __float2half_rn(wx[idx]);
        w[2 + hi] = __float2half_rn(wy[idx]);
    }

    // ---- per-thread constants ----
    const int mbase = (wid & 1) * 32;      // pixel base (2 M-warps)
    const int nbase = (wid >> 1) * 32;     // o base     (4 N-warps)
    const int x3 = gid & 3;

    float bxv[4][2], byv[4][2];
    #pragma unroll
    for (int nt = 0; nt < 4; nt++) {
        int o0 = nbase + nt * 8 + 2 * q;
        bxv[nt][0] = __ldg(bx + o0); bxv[nt][1] = __ldg(bx + o0 + 1);
        byv[nt][0] = __ldg(by + o0); byv[nt][1] = __ldg(by + o0 + 1);
    }

    // A fragment row bases (within a half buffer)
    uint32_t abm[4];
    #pragma unroll
    for (int m = 0; m < 4; m++) {
        int px = mbase + gid + 8 * m;
        abm[m] = (uint32_t)px * 256u + (uint32_t)((q ^ ((px >> 2) & 3)) << 4);
    }
    // B base: row = k16g*8 + q, col = nbase + gid
    const char* pB = smW + q * WPITCH + (nbase + gid) * 8;

    // transform constants: thread handles px = tid&63, q' = tq = tid>>6
    const int px_t = tid & 63;
    const int tq   = tid >> 6;
    const int px3t = px_t & 3;
    const int tqx  = tq ^ ((px_t >> 2) & 3);
    const uint32_t trow = (uint32_t)px_t * 256u;

    // cp.async mapping (raw chunk: 64 c-rows x 544 B)
    const uint32_t cprow = (uint32_t)wid;
    const uint32_t cpcol = (uint32_t)lane * 16u;
    const char* xb = (const char*)x;

    int t = blockIdx.x;

    #define ISSUE(bufoff, tt, ch) do { \
        int _b = (tt) >> 10, _p0 = ((tt) & 1023) << 6; \
        size_t _gb = (((size_t)(_b * 128 + (ch) * 64)) << 19) + ((size_t)_p0 << 3); \
        uint32_t _sb = sbase + (uint32_t)(bufoff) + cpcol; \
        const char* _gp = xb + _gb + cpcol; \
        _Pragma("unroll") \
        for (int _i = 0; _i < 8; _i++) { \
            uint32_t _r = cprow + 8u * _i; \
            cpa16(_sb + _r * 544u, _gp + ((size_t)_r << 19)); \
        } \
        CP_COMMIT(); \
    } while (0)

    // raw[c][px] float2 -> half buffer cells (act_q, act_q4, g_q, g_q4)
    #define TRANSFORM(rawp, hbp) do { \
        _Pragma("unroll") \
        for (int _j = 0; _j < 4; _j++) { \
            const float2* _p = (rawp) + (2 * tq + 16 * _j) * 68 + px_t; \
            float2 _v0 = _p[0]; \
            float2 _v1 = _p[68]; \
            float2 _v2 = _p[8 * 68]; \
            float2 _v3 = _p[9 * 68]; \
            float _g0 = __fdividef(_v0.x * _v0.y, fabsf(_v0.x) + EPSV); \
            float _g1 = __fdividef(_v1.x * _v1.y, fabsf(_v1.x) + EPSV); \
            float _g2 = __fdividef(_v2.x * _v2.y, fabsf(_v2.x) + EPSV); \
            float _g3 = __fdividef(_v3.x * _v3.y, fabsf(_v3.x) + EPSV); \
            uint4 _st; \
            _st.x = h2u(__floats2half2_rn(_v0.x, _v1.x)); \
            _st.y = h2u(__floats2half2_rn(_v2.x, _v3.x)); \
            _st.z = h2u(__floats2half2_rn(_g0, _g1)); \
            _st.w = h2u(__floats2half2_rn(_g2, _g3)); \
            uint32_t _grp = (uint32_t)((((_j ^ px3t) << 2) | tqx) << 4); \
            *(uint4*)((hbp) + trow + _grp) = _st; \
        } \
    } while (0)

    #define MMA_HALF(hb, ch) do { \
        _Pragma("unroll") \
        for (int k16l = 0; k16l < 4; k16l++) { \
            const uint32_t koff = (uint32_t)((k16l ^ x3) << 6); \
            uint4 A0 = *(const uint4*)((hb) + abm[0] + koff); \
            uint4 A1 = *(const uint4*)((hb) + abm[1] + koff); \
            uint4 A2 = *(const uint4*)((hb) + abm[2] + koff); \
            uint4 A3 = *(const uint4*)((hb) + abm[3] + koff); \
            const char* _pb = pB + ((ch) * 4 + k16l) * (8 * WPITCH); \
            _Pragma("unroll") \
            for (int nt = 0; nt < 4; nt++) { \
                uint2 B0 = *(const uint2*)(_pb + nt * 64); \
                uint2 B1 = *(const uint2*)(_pb + 4 * WPITCH + nt * 64); \
                mma_f16(acc[0][0][nt], A0.x, A1.x, A0.y, A1.y, B0.x, B1.x); \
                mma_f16(acc[0][1][nt], A2.x, A3.x, A2.y, A3.y, B0.x, B1.x); \
                mma_f16(acc[1][0][nt], A0.z, A1.z, A0.w, A1.w, B0.y, B1.y); \
                mma_f16(acc[1][1][nt], A2.z, A3.z, A2.w, A3.w, B0.y, B1.y); \
            } \
        } \
    } while (0)

    // ---- prologue: both chunks of first tile in flight ----
    ISSUE(S_RAW0, t, 0);
    ISSUE(S_RAW1, t, 1);

    for (;;) {
        CP_WAIT(1);                 // chunk0(t) arrived
        __syncthreads();
        TRANSFORM(raw0, half0);
        __syncthreads();

        float acc[2][2][4][4];
        #pragma unroll
        for (int g = 0; g < 2; g++)
            #pragma unroll
            for (int mt = 0; mt < 2; mt++)
                #pragma unroll
                for (int nt = 0; nt < 4; nt++)
                    #pragma unroll
                    for (int i = 0; i < 4; i++) acc[g][mt][nt][i] = 0.f;

        MMA_HALF(half0, 0);         // K 0..63

        CP_WAIT(0);                 // chunk1(t) arrived
        __syncthreads();
        const int tn = t + grid;
        if (tn < NTILES) ISSUE(S_RAW0, tn, 0);

        TRANSFORM(raw1, half1);
        __syncthreads();

        MMA_HALF(half1, 1);         // K 64..127

        // ---- epilogue: bias + relu, float2{act, carry} stores ----
        {
            const int b = t >> 10, pp = (t & 1023) << 6;
            const size_t tb = ((size_t)b << 23) + (size_t)pp;
            #pragma unroll
            for (int nt = 0; nt < 4; nt++) {
                const int o0 = nbase + nt * 8 + 2 * q;
                #pragma unroll
                for (int io = 0; io < 2; io++) {
                    float2* rowp = out + tb + ((size_t)(o0 + io) << 16);
                    #pragma unroll
                    for (int mt = 0; mt < 2; mt++) {
                        #pragma unroll
                        for (int ih = 0; ih < 2; ih++) {
                            const int pix = mbase + mt * 16 + gid + ih * 8;
                            float a = acc[0][mt][nt][ih * 2 + io] + bxv[nt][io];
                            float g = acc[1][mt][nt][ih * 2 + io] + byv[nt][io];
                            rowp[pix] = make_float2(fmaxf(a, 0.f), g);
                        }
                    }
                }
            }
        }

        __syncthreads();
        if (tn < NTILES) ISSUE(S_RAW1, tn, 1);
        else break;
        t = tn;
    }
}

extern "C" void kernel_launch(void* const* d_in, const int* in_sizes, int n_in,
                              void* d_out, int out_size) {
    const float* x  = (const float*)d_in[0];
    const float* wx = (const float*)d_in[1];
    const float* bx = (const float*)d_in[2];
    const float* wy = (const float*)d_in[3];
    const float* by = (const float*)d_in[4];
    float2* out = (float2*)d_out;

    int nsm = 148;
    cudaDeviceGetAttribute(&nsm, cudaDevAttrMultiProcessorCount, 0);

    cudaFuncSetAttribute(avnn_h6, cudaFuncAttributeMaxDynamicSharedMemorySize,
                         SMEM_TOTAL);
    avnn_h6<<<nsm, 256, SMEM_TOTAL>>>(x, wx, bx, wy, by, out);
}

// round 7
// speedup vs baseline: 1.9602x; 1.2391x over previous
#include <cuda_runtime.h>
#include <cuda_fp16.h>
#include <cstdint>

#define NTILES 8192            // 524288 pixels / 64 per tile
#define EPSV   1e-6f

// smem byte layout
#define WPITCH   1056
#define S_W      0              // weights: 64 cpair-rows x 1056 B = 67584
#define S_HALF   67584          // 4 stages x 16384 B (64 px x 256 B)
#define S_RAW    133120         // 2 chunks x 34816 B (64 c-rows x 544 B)
#define S_MB     202752         // full[4] @ +0, empty[4] @ +32
#define SMEM_TOTAL 202880

__device__ __forceinline__ void mma_f16(float* c, uint32_t a0, uint32_t a1,
                                        uint32_t a2, uint32_t a3,
                                        uint32_t b0, uint32_t b1) {
    asm volatile(
        "mma.sync.aligned.m16n8k16.row.col.f32.f16.f16.f32 "
        "{%0,%1,%2,%3},{%4,%5,%6,%7},{%8,%9},{%0,%1,%2,%3};\n"
        : "+f"(c[0]), "+f"(c[1]), "+f"(c[2]), "+f"(c[3])
        : "r"(a0), "r"(a1), "r"(a2), "r"(a3), "r"(b0), "r"(b1));
}

__device__ __forceinline__ void cpa16(uint32_t dst, const void* src) {
    asm volatile("cp.async.cg.shared.global [%0], [%1], 16;" :: "r"(dst), "l"(src));
}
#define CP_COMMIT() asm volatile("cp.async.commit_group;" ::: "memory")
#define CP_WAIT1()  asm volatile("cp.async.wait_group 1;" ::: "memory")

__device__ __forceinline__ uint32_t h2u(__half2 h) {
    return *reinterpret_cast<uint32_t*>(&h);
}

#define MB_INIT(addr, cnt) \
    asm volatile("mbarrier.init.shared.b64 [%0], %1;" :: "r"(addr), "r"(cnt) : "memory")
#define MB_ARRIVE(addr) \
    asm volatile("mbarrier.arrive.shared.b64 _, [%0];" :: "r"(addr) : "memory")

#define WAIT_PARITY(addr, ph) do { \
    uint32_t _m = (addr), _p = (ph), _done; \
    asm volatile("{\n\t.reg .pred p;\n\t" \
        "mbarrier.try_wait.parity.acquire.cta.shared::cta.b64 p, [%1], %2;\n\t" \
        "selp.b32 %0, 1, 0, p;\n\t}" : "=r"(_done) : "r"(_m), "r"(_p) : "memory"); \
    if (!_done) { \
        asm volatile("{\n\t.reg .pred P1;\n\t" \
            "WL_%=:\n\t" \
            "mbarrier.try_wait.parity.acquire.cta.shared::cta.b64 P1, [%0], %1, 0x989680;\n\t" \
            "@P1 bra.uni WD_%=;\n\tbra.uni WL_%=;\n\tWD_%=:\n\t}" \
            :: "r"(_m), "r"(_p) : "memory"); \
    } \
} while (0)

__global__ __launch_bounds__(384, 1)
void avnn_w7(const float* __restrict__ x,
             const float* __restrict__ wx,
             const float* __restrict__ bx,
             const float* __restrict__ wy,
             const float* __restrict__ by,
             float2* __restrict__ out) {
    extern __shared__ char smem[];
    uint32_t sbase;
    asm("{ .reg .u64 t; cvta.to.shared.u64 t, %1; cvt.u32.u64 %0, t; }"
        : "=r"(sbase) : "l"((const void*)smem));

    const int tid = threadIdx.x, wid = tid >> 5, lane = tid & 31;
    const int grid = gridDim.x;
    char* smW = smem + S_W;

    // ---- stage weights once: sW[cpair][o] = (wx_lo, wx_hi, wy_lo, wy_hi) ----
    for (int idx = tid; idx < 128 * 128; idx += 384) {
        int o = idx >> 7, c = idx & 127;
        int cp = c >> 1, hi = c & 1;
        __half* w = (__half*)(smW + cp * WPITCH + o * 8);
        w[hi]     = __float2half_rn(wx[idx]);
        w[2 + hi] = __float2half_rn(wy[idx]);
    }
    if (tid == 0) {
        #pragma unroll
        for (int i = 0; i < 4; i++) {
            MB_INIT(sbase + S_MB + i * 8, 128);        // full
            MB_INIT(sbase + S_MB + 32 + i * 8, 256);   // empty
        }
    }
    __syncthreads();

    if (wid >= 8) {
        // ======================= producers (4 warps) =======================
        const int ptid = tid - 256, pwid = ptid >> 5, plane = ptid & 31;
        const char* xb = (const char*)x;
        const uint32_t prow = (uint32_t)(pwid * 16) * 544u + (uint32_t)plane * 16u;

        // issue chunk ch of tile tt into raw buffer rb (this warp's 16 c-rows)
        #define P_ISSUE(rb, tt, ch) do { \
            int _b = (tt) >> 10, _p0 = ((tt) & 1023) << 6; \
            const char* _gp = xb + (((size_t)(_b * 128 + (ch) * 64 + pwid * 16)) << 19) \
                                 + ((size_t)_p0 << 3) + (size_t)plane * 16; \
            uint32_t _sb = sbase + S_RAW + (uint32_t)(rb) * 34816u + prow; \
            _Pragma("unroll") \
            for (int _i = 0; _i < 16; _i++) \
                cpa16(_sb + (uint32_t)_i * 544u, _gp + ((size_t)_i << 19)); \
        } while (0)

        P_ISSUE(0, blockIdx.x, 0); CP_COMMIT();
        P_ISSUE(1, blockIdx.x, 1); CP_COMMIT();

        int s = 0;
        for (int t = blockIdx.x; t < NTILES; t += grid) {
            #pragma unroll
            for (int ch = 0; ch < 2; ch++, s++) {
                CP_WAIT1();
                __syncwarp();
                WAIT_PARITY(sbase + S_MB + 32 + (s & 3) * 8, ((s >> 2) + 1) & 1);

                // transform raw[s&1] (this warp's k16-block j=pwid) -> half[s&3]
                const float2* rp = (const float2*)(smem + S_RAW + (s & 1) * 34816)
                                   + pwid * (16 * 68);
                char* hb = smem + S_HALF + (s & 3) * 16384;
                #pragma unroll
                for (int tqq = 0; tqq < 4; tqq++) {
                    #pragma unroll
                    for (int ph = 0; ph < 2; ph++) {
                        const int px = plane + 32 * ph;
                        const float2* p0 = rp + 2 * tqq * 68 + px;
                        float2 v0 = p0[0];
                        float2 v1 = p0[68];
                        float2 v2 = p0[8 * 68];
                        float2 v3 = p0[9 * 68];
                        float g0 = __fdividef(v0.x * v0.y, fabsf(v0.x) + EPSV);
                        float g1 = __fdividef(v1.x * v1.y, fabsf(v1.x) + EPSV);
                        float g2 = __fdividef(v2.x * v2.y, fabsf(v2.x) + EPSV);
                        float g3 = __fdividef(v3.x * v3.y, fabsf(v3.x) + EPSV);
                        uint4 st;
                        st.x = h2u(__floats2half2_rn(v0.x, v1.x));
                        st.y = h2u(__floats2half2_rn(v2.x, v3.x));
                        st.z = h2u(__floats2half2_rn(g0, g1));
                        st.w = h2u(__floats2half2_rn(g2, g3));
                        uint32_t slot = (uint32_t)(((pwid ^ (px & 3)) << 2)
                                                   | (tqq ^ ((px >> 1) & 3)));
                        *(uint4*)(hb + px * 256 + slot * 16) = st;
                    }
                }
                MB_ARRIVE(sbase + S_MB + (s & 3) * 8);

                int tn = t + grid;
                if (tn < NTILES) P_ISSUE(s & 1, tn, ch);
                CP_COMMIT();
            }
        }
    } else {
        // ======================= consumers (8 warps) =======================
        const int gid = lane >> 2, q = lane & 3;
        const int mbase = (wid & 1) * 32;      // pixel base (2 M-warps)
        const int nbase = (wid >> 1) * 32;     // o base     (4 N-warps)
        const int x3 = gid & 3;

        float bxv[4][2], byv[4][2];
        #pragma unroll
        for (int nt = 0; nt < 4; nt++) {
            int o0 = nbase + nt * 8 + 2 * q;
            bxv[nt][0] = __ldg(bx + o0); bxv[nt][1] = __ldg(bx + o0 + 1);
            byv[nt][0] = __ldg(by + o0); byv[nt][1] = __ldg(by + o0 + 1);
        }

        uint32_t abm[4];
        #pragma unroll
        for (int m = 0; m < 4; m++) {
            int px = mbase + gid + 8 * m;
            abm[m] = (uint32_t)px * 256u + (uint32_t)((q ^ (gid >> 1)) << 4);
        }
        const char* pB = smW + q * WPITCH + (nbase + gid) * 8;

        int s = 0;
        for (int t = blockIdx.x; t < NTILES; t += grid) {
            float acc[2][2][4][4];
            #pragma unroll
            for (int g = 0; g < 2; g++)
                #pragma unroll
                for (int mt = 0; mt < 2; mt++)
                    #pragma unroll
                    for (int nt = 0; nt < 4; nt++)
                        #pragma unroll
                        for (int i = 0; i < 4; i++) acc[g][mt][nt][i] = 0.f;

            #pragma unroll
            for (int ch = 0; ch < 2; ch++, s++) {
                WAIT_PARITY(sbase + S_MB + (s & 3) * 8, (s >> 2) & 1);
                const char* hb = smem + S_HALF + (s & 3) * 16384;

                #pragma unroll
                for (int k16l = 0; k16l < 4; k16l++) {
                    const uint32_t koff = (uint32_t)((k16l ^ x3) << 6);
                    uint4 A0 = *(const uint4*)(hb + abm[0] + koff);
                    uint4 A1 = *(const uint4*)(hb + abm[1] + koff);
                    uint4 A2 = *(const uint4*)(hb + abm[2] + koff);
                    uint4 A3 = *(const uint4*)(hb + abm[3] + koff);
                    const char* _pb = pB + (ch * 4 + k16l) * (8 * WPITCH);
                    #pragma unroll
                    for (int nt = 0; nt < 4; nt++) {
                        uint2 B0 = *(const uint2*)(_pb + nt * 64);
                        uint2 B1 = *(const uint2*)(_pb + 4 * WPITCH + nt * 64);
                        mma_f16(acc[0][0][nt], A0.x, A1.x, A0.y, A1.y, B0.x, B1.x);
                        mma_f16(acc[0][1][nt], A2.x, A3.x, A2.y, A3.y, B0.x, B1.x);
                        mma_f16(acc[1][0][nt], A0.z, A1.z, A0.w, A1.w, B0.y, B1.y);
                        mma_f16(acc[1][1][nt], A2.z, A3.z, A2.w, A3.w, B0.y, B1.y);
                    }
                }
                MB_ARRIVE(sbase + S_MB + 32 + (s & 3) * 8);
            }

            // ---- epilogue ----
            const int b = t >> 10, pp = (t & 1023) << 6;
            const size_t tb = ((size_t)b << 23) + (size_t)pp;
            #pragma unroll
            for (int nt = 0; nt < 4; nt++) {
                const int o0 = nbase + nt * 8 + 2 * q;
                #pragma unroll
                for (int io = 0; io < 2; io++) {
                    float2* rowp = out + tb + ((size_t)(o0 + io) << 16);
                    #pragma unroll
                    for (int mt = 0; mt < 2; mt++) {
                        #pragma unroll
                        for (int ih = 0; ih < 2; ih++) {
                            const int pix = mbase + mt * 16 + gid + ih * 8;
                            float a = acc[0][mt][nt][ih * 2 + io] + bxv[nt][io];
                            float g = acc[1][mt][nt][ih * 2 + io] + byv[nt][io];
                            rowp[pix] = make_float2(fmaxf(a, 0.f), g);
                        }
                    }
                }
            }
        }
    }
}

extern "C" void kernel_launch(void* const* d_in, const int* in_sizes, int n_in,
                              void* d_out, int out_size) {
    const float* x  = (const float*)d_in[0];
    const float* wx = (const float*)d_in[1];
    const float* bx = (const float*)d_in[2];
    const float* wy = (const float*)d_in[3];
    const float* by = (const float*)d_in[4];
    float2* out = (float2*)d_out;

    int nsm = 148;
    cudaDeviceGetAttribute(&nsm, cudaDevAttrMultiProcessorCount, 0);

    cudaFuncSetAttribute(avnn_w7, cudaFuncAttributeMaxDynamicSharedMemorySize,
                         SMEM_TOTAL);
    avnn_w7<<<nsm, 384, SMEM_TOTAL>>>(x, wx, bx, wy, by, out);
}